// round 3
// baseline (speedup 1.0000x reference)
#include <cuda_runtime.h>

// Problem constants
#define BSZ     8
#define KDIM    4096
#define NDIM    11008
#define RPW     8                       // rows per warp task
#define SPLITK  4
#define KCH     (KDIM / SPLITK)         // 1024 floats per K-chunk
#define KITERS  (KCH / 128)             // 8 iterations (warp covers 128 floats/iter)
#define WARPS_PER_CTA 8
#define THREADS (WARPS_PER_CTA * 32)    // 256
#define NCTAS   148
#define TOTAL_WARPS (NCTAS * WARPS_PER_CTA)   // 1184
#define NROWGROUPS (NDIM / RPW)               // 1376
#define NTASKS  (NROWGROUPS * SPLITK)         // 5504
#define SMEM_BYTES (BSZ * KDIM * 4)           // 131072

// ---- packed f32x2 FMA (Blackwell f32x2 pipe) ----
__device__ __forceinline__ void ffma2(unsigned long long& d,
                                      unsigned long long a,
                                      unsigned long long b) {
    asm("fma.rn.f32x2 %0, %1, %2, %0;" : "+l"(d) : "l"(a), "l"(b));
}
__device__ __forceinline__ float sum2(unsigned long long a) {
    float lo, hi;
    asm("mov.b64 {%0, %1}, %2;" : "=f"(lo), "=f"(hi) : "l"(a));
    return lo + hi;
}
// streaming 128-bit global load as two packed f32x2 words
__device__ __forceinline__ void ldg_cs_v2u64(const void* p,
                                             unsigned long long& a,
                                             unsigned long long& b) {
    asm("ld.global.cs.v2.u64 {%0, %1}, [%2];"
        : "=l"(a), "=l"(b) : "l"(p));
}

extern __shared__ float xs[];   // [BSZ][KDIM] staged activations

__global__ __launch_bounds__(THREADS, 1)
void asl_gemv_kernel(const float* __restrict__ x,
                     const float* __restrict__ w,
                     float* __restrict__ out) {
    // ---- stage x into shared memory (131 KB), once per CTA ----
    {
        const float4* x4  = reinterpret_cast<const float4*>(x);
        float4*       xs4 = reinterpret_cast<float4*>(xs);
        #pragma unroll 8
        for (int i = threadIdx.x; i < BSZ * KDIM / 4; i += THREADS)
            xs4[i] = x4[i];
    }
    __syncthreads();

    const int lane  = threadIdx.x & 31;
    const int gwarp = blockIdx.x * WARPS_PER_CTA + (threadIdx.x >> 5);
    const ulonglong2* xs2 = reinterpret_cast<const ulonglong2*>(xs);

    for (int task = gwarp; task < NTASKS; task += TOTAL_WARPS) {
        const int rg    = task / SPLITK;      // row group
        const int kc    = task % SPLITK;      // K-chunk (constant per warp)
        const int n0    = rg * RPW;
        const int kbase = kc * KCH;           // float offset into K

        const char* wr = reinterpret_cast<const char*>(
            w + (size_t)n0 * KDIM + kbase);
        const ulonglong2* xb = xs2 + (kbase >> 2);  // x chunk base (16B units)

        unsigned long long acc[RPW][BSZ];
        #pragma unroll
        for (int r = 0; r < RPW; r++)
            #pragma unroll
            for (int b = 0; b < BSZ; b++)
                acc[r][b] = 0ULL;

        // ---- manual double-buffered weight prefetch ----
        unsigned long long wc[RPW][2], wn[RPW][2];
        {
            const int koff = lane * 16;
            #pragma unroll
            for (int r = 0; r < RPW; r++)
                ldg_cs_v2u64(wr + (size_t)r * KDIM * 4 + koff, wc[r][0], wc[r][1]);
        }

        #pragma unroll
        for (int it = 0; it < KITERS; it++) {
            if (it + 1 < KITERS) {
                const int koff = ((it + 1) * 32 + lane) * 16;
                #pragma unroll
                for (int r = 0; r < RPW; r++)
                    ldg_cs_v2u64(wr + (size_t)r * KDIM * 4 + koff,
                                 wn[r][0], wn[r][1]);
            }

            const int xoff = it * 32 + lane;          // 16B-unit offset
            #pragma unroll
            for (int b = 0; b < BSZ; b++) {
                ulonglong2 xv = xb[b * (KDIM / 4) + xoff];
                #pragma unroll
                for (int r = 0; r < RPW; r++) {
                    ffma2(acc[r][b], wc[r][0], xv.x);
                    ffma2(acc[r][b], wc[r][1], xv.y);
                }
            }

            #pragma unroll
            for (int r = 0; r < RPW; r++) {
                wc[r][0] = wn[r][0];
                wc[r][1] = wn[r][1];
            }
        }

        // ---- warp reduction: collapse f32x2 -> f32, then 5-step shfl_down ----
        float vals[RPW][BSZ];
        #pragma unroll
        for (int r = 0; r < RPW; r++) {
            #pragma unroll
            for (int b = 0; b < BSZ; b++) {
                float s = sum2(acc[r][b]);
                s += __shfl_down_sync(0xFFFFFFFFu, s, 16);
                s += __shfl_down_sync(0xFFFFFFFFu, s, 8);
                s += __shfl_down_sync(0xFFFFFFFFu, s, 4);
                s += __shfl_down_sync(0xFFFFFFFFu, s, 2);
                s += __shfl_down_sync(0xFFFFFFFFu, s, 1);
                vals[r][b] = s;
            }
        }

        // ---- split-K accumulation directly into out via RED.ADD ----
        if (lane == 0) {
            #pragma unroll
            for (int b = 0; b < BSZ; b++)
                #pragma unroll
                for (int r = 0; r < RPW; r++)
                    atomicAdd(out + (size_t)b * NDIM + n0 + r, vals[r][b]);
        }
    }
}

// zero-init the output (poisoned to 0xAA by harness)
__global__ void asl_zero_kernel(float* __restrict__ out) {
    const int i = blockIdx.x * blockDim.x + threadIdx.x;   // float4 index
    const int total4 = BSZ * NDIM / 4;                     // 22016
    if (i < total4)
        reinterpret_cast<float4*>(out)[i] = make_float4(0.f, 0.f, 0.f, 0.f);
}

extern "C" void kernel_launch(void* const* d_in, const int* in_sizes, int n_in,
                              void* d_out, int out_size) {
    const float* x = (const float*)d_in[0];
    const float* w = (const float*)d_in[1];
    if (n_in >= 2 && in_sizes[0] == NDIM * KDIM) {   // defensive order fix
        const float* t = x; x = w; w = t;
    }
    float* out = (float*)d_out;

    cudaFuncSetAttribute(asl_gemv_kernel,
                         cudaFuncAttributeMaxDynamicSharedMemorySize,
                         SMEM_BYTES);

    const int total4 = BSZ * NDIM / 4;
    asl_zero_kernel<<<(total4 + 511) / 512, 512>>>(out);
    asl_gemv_kernel<<<NCTAS, THREADS, SMEM_BYTES>>>(x, w, out);
}